// round 3
// baseline (speedup 1.0000x reference)
#include <cuda_runtime.h>
#include <math.h>

// Problem constants: B=16, C=512, H=W=64, G=16, CPG=32, HID=8
#define BN   16
#define CN   512
#define GN   16
#define CPGN 32
#define HIDN 8
#define HWN  4096   // 64*64
#define NIMG (BN * CN)      // 8192 channel-images
#define GRID 148            // <= SM count: 1 CTA/SM residency guaranteed
#define NWARP (GRID * 32)   // 4736 warps total

__device__ float g_pooled[NIMG];
__device__ float g_scale[NIMG];
__device__ unsigned g_barcnt = 0;
__device__ volatile unsigned g_sense = 0;

__device__ __forceinline__ float sigmoidf_(float v) {
    return 1.0f / (1.0f + expf(-v));
}

// Grid-wide sense-reversal barrier. All GRID blocks co-resident (1 CTA/SM).
__device__ __forceinline__ void grid_barrier() {
    __syncthreads();
    if (threadIdx.x == 0) {
        __threadfence();                    // publish my writes
        unsigned s0 = g_sense;              // read sense BEFORE arriving
        unsigned r = atomicAdd(&g_barcnt, 1u);
        if (r == GRID - 1) {
            g_barcnt = 0;
            __threadfence();
            g_sense = s0 + 1;               // release everyone
        } else {
            while (g_sense == s0) { }       // spin
        }
        __threadfence();                    // acquire
    }
    __syncthreads();
}

__global__ __launch_bounds__(1024, 1)
void fused_kernel(const float* __restrict__ x, float* __restrict__ out,
                  const float* __restrict__ gw1, const float* __restrict__ gb1,
                  const float* __restrict__ gw2, const float* __restrict__ gb2,
                  const float* __restrict__ cw1, const float* __restrict__ cb1,
                  const float* __restrict__ cw2, const float* __restrict__ cb2) {
    const int tid  = threadIdx.x;
    const int lane = tid & 31;
    const int wgl  = blockIdx.x * 32 + (tid >> 5);   // global warp id

    // ---------------- Phase A: spatial mean per (b,c), one warp per image ----
    for (int img = wgl; img < NIMG; img += NWARP) {
        const float4* p = reinterpret_cast<const float4*>(x + (size_t)img * HWN);
        float s = 0.f;
#pragma unroll 8
        for (int i = 0; i < 32; i++) {
            float4 v = p[lane + i * 32];
            s += (v.x + v.y) + (v.z + v.w);
        }
#pragma unroll
        for (int o = 16; o; o >>= 1) s += __shfl_down_sync(0xffffffffu, s, o);
        if (lane == 0) g_pooled[img] = s * (1.0f / HWN);
    }

    grid_barrier();

    // ---------------- Phase B: gating math, blocks 0..15 = batches ----------
    // IMPORTANT: every __syncthreads() here is executed by ALL 1024 threads of
    // the participating blocks; only the compute is guarded by tid < CN.
    if (blockIdx.x < BN) {
        const int b = blockIdx.x;
        const int g = tid >> 5, c = tid & 31;   // only meaningful for tid < CN

        __shared__ float pooled1[CN], gate1[CN], pooled2[CN], gate2[CN];
        __shared__ float h[GN][HIDN];
        __shared__ float glob[GN], wv[GN], hc[HIDN];

        if (tid < CN) pooled1[tid] = g_pooled[b * CN + tid];
        __syncthreads();

        // SE pass 1 (original channel order)
        if (tid < CN && c < HIDN) {
            float s = gb1[c];
#pragma unroll
            for (int j = 0; j < CPGN; j++) s += pooled1[g * CPGN + j] * gw1[c * CPGN + j];
            h[g][c] = fmaxf(s, 0.f);
        }
        __syncthreads();
        if (tid < CN) {
            float s = gb2[c];
#pragma unroll
            for (int o = 0; o < HIDN; o++) s += h[g][o] * gw2[c * HIDN + o];
            gate1[tid] = sigmoidf_(s);
        }
        __syncthreads();

        // channel shuffle on pooled values
        if (tid < CN) {
            const int g1 = tid & 15, cpg1 = tid >> 4;
            const int och = g1 * CPGN + cpg1;
            pooled2[tid] = pooled1[och] * gate1[och];
        }
        __syncthreads();

        // SE pass 2 (shuffled order)
        if (tid < CN && c < HIDN) {
            float s = gb1[c];
#pragma unroll
            for (int j = 0; j < CPGN; j++) s += pooled2[g * CPGN + j] * gw1[c * CPGN + j];
            h[g][c] = fmaxf(s, 0.f);
        }
        __syncthreads();
        if (tid < CN) {
            float s = gb2[c];
#pragma unroll
            for (int o = 0; o < HIDN; o++) s += h[g][o] * gw2[c * HIDN + o];
            gate2[tid] = sigmoidf_(s);
        }
        __syncthreads();

        // cross-group gate
        if (tid < GN) {
            float s = 0.f;
#pragma unroll
            for (int j = 0; j < CPGN; j++) s += pooled2[tid * CPGN + j] * gate2[tid * CPGN + j];
            glob[tid] = s * (1.0f / CPGN);
        }
        __syncthreads();
        if (tid < HIDN) {
            float s = cb1[tid];
#pragma unroll
            for (int j = 0; j < GN; j++) s += glob[j] * cw1[tid * GN + j];
            hc[tid] = fmaxf(s, 0.f);
        }
        __syncthreads();
        if (tid < GN) {
            float s = cb2[tid];
#pragma unroll
            for (int o = 0; o < HIDN; o++) s += hc[o] * cw2[tid * HIDN + o];
            wv[tid] = sigmoidf_(s);
        }
        __syncthreads();

        // final per-output-channel scale
        if (tid < CN) {
            const int g2 = tid >> 5, c2 = tid & 31;       // tid == ch2
            const int g1 = tid & 15, cpg1 = tid >> 4;
            const int och = g1 * CPGN + cpg1;
            const float s = gate1[och] * gate2[tid] * wv[g2];
            const int ch_out = c2 * GN + g2;
            g_scale[b * CN + ch_out] = s;
        }
    }

    grid_barrier();

    // ---------------- Phase C: out[b,ch_out] = x[b,ch_orig] * scale --------
    // Reverse iteration: consume the x tail still L2-resident from phase A
    // first. __stcs on output keeps the streaming writes from evicting x.
    for (int k = wgl; k < NIMG; k += NWARP) {
        const int bc = NIMG - 1 - k;            // b*512 + ch_out, descending
        const int b = bc >> 9;
        const int ch_out = bc & 511;
        const int c2 = ch_out >> 4, g2 = ch_out & 15;
        const int ch2 = g2 * CPGN + c2;
        const int g1 = ch2 & 15, cpg1 = ch2 >> 4;
        const int och = g1 * CPGN + cpg1;

        const float s = g_scale[bc];
        const float4* pin = reinterpret_cast<const float4*>(x + ((size_t)b * CN + och) * HWN);
        float4* pout = reinterpret_cast<float4*>(out + (size_t)bc * HWN);
#pragma unroll 8
        for (int i = 0; i < 32; i++) {
            float4 v = __ldcs(&pin[lane + i * 32]);
            v.x *= s; v.y *= s; v.z *= s; v.w *= s;
            __stcs(&pout[lane + i * 32], v);
        }
    }
}

extern "C" void kernel_launch(void* const* d_in, const int* in_sizes, int n_in,
                              void* d_out, int out_size) {
    const float* x   = (const float*)d_in[0];
    const float* gw1 = (const float*)d_in[1];
    const float* gb1 = (const float*)d_in[2];
    const float* gw2 = (const float*)d_in[3];
    const float* gb2 = (const float*)d_in[4];
    const float* cw1 = (const float*)d_in[5];
    const float* cb1 = (const float*)d_in[6];
    const float* cw2 = (const float*)d_in[7];
    const float* cb2 = (const float*)d_in[8];
    float* out = (float*)d_out;

    fused_kernel<<<GRID, 1024>>>(x, out, gw1, gb1, gw2, gb2, cw1, cb1, cw2, cb2);
}

// round 4
// speedup vs baseline: 1.3229x; 1.3229x over previous
#include <cuda_runtime.h>
#include <math.h>

// Problem constants: B=16, C=512, H=W=64, G=16, CPG=32, HID=8
#define BN   16
#define CN   512
#define GN   16
#define CPGN 32
#define HIDN 8
#define HWN  4096   // 64*64
#define NIMG (BN * CN)

__device__ float g_pooled[NIMG];
__device__ float g_scale[NIMG];

// ---------------------------------------------------------------------------
// Kernel 1: spatial mean per (b, c). One block per channel-image.
// Streams x in ASCENDING image order -> tail of x left resident in L2.
// ---------------------------------------------------------------------------
__global__ void pool_kernel(const float* __restrict__ x) {
    const int bc = blockIdx.x;  // 0 .. 8191
    const float4* p = reinterpret_cast<const float4*>(x + (size_t)bc * HWN);
    float s = 0.f;
#pragma unroll
    for (int i = 0; i < 4; i++) {
        float4 v = p[threadIdx.x + i * 256];
        s += (v.x + v.y) + (v.z + v.w);
    }
#pragma unroll
    for (int o = 16; o; o >>= 1) s += __shfl_down_sync(0xffffffffu, s, o);
    __shared__ float ws[8];
    if ((threadIdx.x & 31) == 0) ws[threadIdx.x >> 5] = s;
    __syncthreads();
    if (threadIdx.x == 0) {
        float t = 0.f;
#pragma unroll
        for (int i = 0; i < 8; i++) t += ws[i];
        g_pooled[bc] = t * (1.0f / HWN);
    }
}

// ---------------------------------------------------------------------------
// Kernel 2: all gating math. One block per batch, 512 threads = 512 channels.
// ---------------------------------------------------------------------------
__device__ __forceinline__ float sigmoidf_(float v) {
    return 1.0f / (1.0f + expf(-v));
}

__global__ void gate_kernel(const float* __restrict__ gw1, const float* __restrict__ gb1,
                            const float* __restrict__ gw2, const float* __restrict__ gb2,
                            const float* __restrict__ cw1, const float* __restrict__ cb1,
                            const float* __restrict__ cw2, const float* __restrict__ cb2) {
    const int b = blockIdx.x;
    const int tid = threadIdx.x;          // 0..511
    const int g = tid >> 5, c = tid & 31;

    __shared__ float pooled1[CN], gate1[CN], pooled2[CN], gate2[CN];
    __shared__ float h[GN][HIDN];
    __shared__ float glob[GN], wv[GN], hc[HIDN];

    pooled1[tid] = g_pooled[b * CN + tid];
    __syncthreads();

    // SE pass 1 (original channel order)
    if (c < HIDN) {
        float s = gb1[c];
#pragma unroll
        for (int j = 0; j < CPGN; j++) s += pooled1[g * CPGN + j] * gw1[c * CPGN + j];
        h[g][c] = fmaxf(s, 0.f);
    }
    __syncthreads();
    {
        float s = gb2[c];
#pragma unroll
        for (int o = 0; o < HIDN; o++) s += h[g][o] * gw2[c * HIDN + o];
        gate1[tid] = sigmoidf_(s);
    }
    __syncthreads();

    // channel shuffle on pooled values: ch2 -> ch_orig
    {
        const int g1 = tid & 15, cpg1 = tid >> 4;
        const int och = g1 * CPGN + cpg1;
        pooled2[tid] = pooled1[och] * gate1[och];
    }
    __syncthreads();

    // SE pass 2 (shuffled order)
    if (c < HIDN) {
        float s = gb1[c];
#pragma unroll
        for (int j = 0; j < CPGN; j++) s += pooled2[g * CPGN + j] * gw1[c * CPGN + j];
        h[g][c] = fmaxf(s, 0.f);
    }
    __syncthreads();
    {
        float s = gb2[c];
#pragma unroll
        for (int o = 0; o < HIDN; o++) s += h[g][o] * gw2[c * HIDN + o];
        gate2[tid] = sigmoidf_(s);
    }
    __syncthreads();

    // cross-group gate
    if (tid < GN) {
        float s = 0.f;
#pragma unroll
        for (int j = 0; j < CPGN; j++) s += pooled2[tid * CPGN + j] * gate2[tid * CPGN + j];
        glob[tid] = s * (1.0f / CPGN);
    }
    __syncthreads();
    if (tid < HIDN) {
        float s = cb1[tid];
#pragma unroll
        for (int j = 0; j < GN; j++) s += glob[j] * cw1[tid * GN + j];
        hc[tid] = fmaxf(s, 0.f);
    }
    __syncthreads();
    if (tid < GN) {
        float s = cb2[tid];
#pragma unroll
        for (int o = 0; o < HIDN; o++) s += hc[o] * cw2[tid * HIDN + o];
        wv[tid] = sigmoidf_(s);
    }
    __syncthreads();

    // compose final per-channel scale, store indexed by output channel
    {
        const int g2 = tid >> 5, c2 = tid & 31;  // tid == ch2
        const int g1 = tid & 15, cpg1 = tid >> 4;
        const int och = g1 * CPGN + cpg1;
        const float s = gate1[och] * gate2[tid] * wv[g2];
        const int ch_out = c2 * GN + g2;
        g_scale[b * CN + ch_out] = s;
    }
}

// ---------------------------------------------------------------------------
// Kernel 3: out[b, ch_out] = x[b, ch_orig] * scale[b, ch_out].
// REVERSED block->image mapping: first waves consume the x tail still
// resident in L2 from the pool kernel. __stcs (evict-first) output stores
// keep the streaming writes from evicting x lines.
// ---------------------------------------------------------------------------
__global__ void scale_kernel(const float* __restrict__ x, float* __restrict__ out) {
    const int bc = NIMG - 1 - blockIdx.x;  // b*512 + ch_out, descending
    const int b = bc >> 9;
    const int ch_out = bc & 511;
    const int c2 = ch_out >> 4, g2 = ch_out & 15;
    const int ch2 = g2 * CPGN + c2;
    const int g1 = ch2 & 15, cpg1 = ch2 >> 4;
    const int och = g1 * CPGN + cpg1;

    const float s = g_scale[bc];
    const float4* pin  = reinterpret_cast<const float4*>(x + ((size_t)b * CN + och) * HWN);
    float4* pout = reinterpret_cast<float4*>(out + (size_t)bc * HWN);
#pragma unroll
    for (int i = 0; i < 4; i++) {
        float4 v = pin[threadIdx.x + i * 256];
        v.x *= s; v.y *= s; v.z *= s; v.w *= s;
        __stcs(&pout[threadIdx.x + i * 256], v);
    }
}

extern "C" void kernel_launch(void* const* d_in, const int* in_sizes, int n_in,
                              void* d_out, int out_size) {
    const float* x   = (const float*)d_in[0];
    const float* gw1 = (const float*)d_in[1];
    const float* gb1 = (const float*)d_in[2];
    const float* gw2 = (const float*)d_in[3];
    const float* gb2 = (const float*)d_in[4];
    const float* cw1 = (const float*)d_in[5];
    const float* cb1 = (const float*)d_in[6];
    const float* cw2 = (const float*)d_in[7];
    const float* cb2 = (const float*)d_in[8];
    float* out = (float*)d_out;

    pool_kernel<<<NIMG, 256>>>(x);
    gate_kernel<<<BN, CN>>>(gw1, gb1, gw2, gb2, cw1, cb1, cw2, cb2);
    scale_kernel<<<NIMG, 256>>>(x, out);
}